// round 10
// baseline (speedup 1.0000x reference)
#include <cuda_runtime.h>

#define WID 512
#define NT  180
#define SEG 8
#define RPS (WID / SEG)   // 64 rows per segment
#define PW  513           // padded row width in float4 entries

// Pair tables: entry e of row y holds (v0[y][e-1], v1[y][e-1], v0[y][e], v1[y][e]),
// with out-of-range pixels = 0. PN = natural orientation, PT = transposed.
__device__ float4 g_PN[WID * PW];
__device__ float4 g_PT[WID * PW];
// scratch partial sums: [SEG][2][512 cols][180 thetas]
__device__ float g_scratch[SEG * 2 * WID * NT];

// ── pack prepass ── grid (3, 512, 2), block 256; z=0 builds PN, z=1 builds PT
__global__ __launch_bounds__(256) void pack_kernel(const float* __restrict__ img)
{
    const int e   = blockIdx.x * 256 + threadIdx.x;   // 0..512
    const int row = blockIdx.y;
    if (e >= PW) return;

    const float* __restrict__ i0 = img;
    const float* __restrict__ i1 = img + WID * WID;

    float a0 = 0.f, a1 = 0.f, b0 = 0.f, b1 = 0.f;
    if (blockIdx.z == 0) {
        // PN[row][e]: pixels img[row][e-1], img[row][e]
        if (e >= 1)   { a0 = i0[row * WID + e - 1]; a1 = i1[row * WID + e - 1]; }
        if (e < WID)  { b0 = i0[row * WID + e];     b1 = i1[row * WID + e];     }
        g_PN[row * PW + e] = make_float4(a0, a1, b0, b1);
    } else {
        // PT[row][e]: pixels imgT[row][e-1], imgT[row][e] = img[e-1][row], img[e][row]
        if (e >= 1)   { a0 = i0[(e - 1) * WID + row]; a1 = i1[(e - 1) * WID + row]; }
        if (e < WID)  { b0 = i0[e * WID + row];       b1 = i1[e * WID + row];       }
        g_PT[row * PW + e] = make_float4(a0, a1, b0, b1);
    }
}

// ── main kernel ── grid (2, NT, SEG), block 256; each thread: one column c, both batches.
__global__ __launch_bounds__(256) void radon_part_kernel()
{
    const int t   = blockIdx.y;
    const int seg = blockIdx.z;
    const int c   = blockIdx.x * 256 + threadIdx.x;

    const float th = (float)t * 0.017453292519943295f;
    float s, co;
    sincosf(th, &s, &co);

    const float u = (float)c - 255.5f;
    // ix(r) = co*u + s*r + Kx ; iy(r) = -s*u + co*r + Ky
    const float ix0 = fmaf(co, u, fmaf(s, -255.5f, 255.5f));
    const float iy0 = fmaf(-s, u, fmaf(co, -255.5f, 255.5f));

    // steep angles: sample the transposed table with swapped coords so that
    // warp-adjacent lanes read memory-adjacent addresses.
    const bool steep = fabsf(s) > fabsf(co);
    float x0c, y0c, stepx, stepy;
    const float4* __restrict__ P;
    if (!steep) { x0c = ix0; y0c = iy0; stepx = s;  stepy = co; P = g_PN; }
    else        { x0c = iy0; y0c = ix0; stepx = co; stepy = s;  P = g_PT; }

    // clip r to where the sample can contribute: coord in (-1, 512) on both axes.
    float lo = 0.0f, hi = (float)WID;
    {
        if (fabsf(stepx) < 1e-6f) {
            if (x0c <= -1.0f || x0c >= (float)WID) { lo = 1.0f; hi = 0.0f; }
        } else {
            const float a = (-1.0f - x0c) / stepx;
            const float b = ((float)WID - x0c) / stepx;
            lo = fmaxf(lo, fminf(a, b));
            hi = fminf(hi, fmaxf(a, b));
        }
        if (fabsf(stepy) < 1e-6f) {
            if (y0c <= -1.0f || y0c >= (float)WID) { lo = 1.0f; hi = 0.0f; }
        } else {
            const float a = (-1.0f - y0c) / stepy;
            const float b = ((float)WID - y0c) / stepy;
            lo = fmaxf(lo, fminf(a, b));
            hi = fminf(hi, fmaxf(a, b));
        }
    }
    const int rbeg = seg * RPS;
    int r0 = rbeg, r1 = rbeg + RPS;
    // expand by 1 each side; in-loop predicates keep correctness regardless.
    if (lo > (float)r0 + 1.0f) r0 = (int)floorf(lo) - 1;
    if (hi < (float)r1 - 1.0f) r1 = (int)ceilf(hi) + 1;
    if (r1 > rbeg + RPS) r1 = rbeg + RPS;
    if (r0 < rbeg) r0 = rbeg;

    float sum0 = 0.0f, sum1 = 0.0f;

#pragma unroll 4
    for (int r = r0; r < r1; ++r) {
        const float fr = (float)r;
        const float xx = fmaf(fr, stepx, x0c);
        const float yy = fmaf(fr, stepy, y0c);

        const float fx0 = floorf(xx);
        const float fy0 = floorf(yy);
        const float tx = xx - fx0;
        const float ty = yy - fy0;

        const int x0 = (int)fx0;
        const int y0 = (int)fy0;

        const int  e   = x0 + 1;                       // entry index: pixels (x0, x0+1)
        const bool px  = (unsigned)e        < (unsigned)PW;   // x0 in [-1, 511]
        const bool vy0 = (unsigned)y0       < (unsigned)WID;
        const bool vy1 = (unsigned)(y0 + 1) < (unsigned)WID;

        const int base = y0 * PW + e;

        float4 T = make_float4(0.f, 0.f, 0.f, 0.f);
        float4 Bm = make_float4(0.f, 0.f, 0.f, 0.f);
        if (px & vy0) T  = __ldg(P + base);
        if (px & vy1) Bm = __ldg(P + base + PW);

        // T = (A0, A1, B0, B1) of top row; Bm likewise for bottom row
        const float top0 = fmaf(tx, T.z - T.x, T.x);
        const float top1 = fmaf(tx, T.w - T.y, T.y);
        const float bot0 = fmaf(tx, Bm.z - Bm.x, Bm.x);
        const float bot1 = fmaf(tx, Bm.w - Bm.y, Bm.y);

        sum0 += fmaf(ty, bot0 - top0, top0);
        sum1 += fmaf(ty, bot1 - top1, top1);
    }

    g_scratch[((seg * 2 + 0) * WID + c) * NT + t] = sum0;
    g_scratch[((seg * 2 + 1) * WID + c) * NT + t] = sum1;
}

// out[n][c][t] = (1/512) * sum_seg scratch[seg][n][c][t]
__global__ __launch_bounds__(256) void radon_reduce_kernel(
    float* __restrict__ out)         // [2, 512, 180] = 184320 elems
{
    const int i = blockIdx.x * 256 + threadIdx.x;
    const int n   = i / (WID * NT);
    const int rem = i - n * (WID * NT);

    float acc = 0.0f;
#pragma unroll
    for (int seg = 0; seg < SEG; ++seg)
        acc += g_scratch[(seg * 2 + n) * (WID * NT) + rem];

    out[i] = acc * (1.0f / (float)WID);
}

extern "C" void kernel_launch(void* const* d_in, const int* in_sizes, int n_in,
                              void* d_out, int out_size)
{
    const float* x = (const float*)d_in[0];   // [2,1,512,512] fp32
    float* out = (float*)d_out;               // [2,1,512,180] fp32

    pack_kernel<<<dim3(3, WID, 2), 256>>>(x);
    radon_part_kernel<<<dim3(2, NT, SEG), 256>>>();
    radon_reduce_kernel<<<(2 * WID * NT) / 256, 256>>>(out);
}

// round 12
// speedup vs baseline: 1.0064x; 1.0064x over previous
#include <cuda_runtime.h>

#define WID 512
#define NT  180
#define SEG 8
#define RPS (WID / SEG)   // 64 rows per segment

// interleaved pair images: pairN[y*512+x] = (img0[y][x], img1[y][x]); pairT = transposed
__device__ float2 g_pairN[WID * WID];
__device__ float2 g_pairT[WID * WID];
// scratch partial sums: [SEG][2][512 cols][180 thetas]
__device__ float g_scratch[SEG * 2 * WID * NT];

// ── pack + transpose prepass ── grid (16,16), block (32,8)
__global__ __launch_bounds__(256) void pack_kernel(const float* __restrict__ img)
{
    __shared__ float t0[32][33];
    __shared__ float t1[32][33];

    int x = blockIdx.x * 32 + threadIdx.x;
    int y = blockIdx.y * 32 + threadIdx.y;
#pragma unroll
    for (int j = 0; j < 32; j += 8) {
        const float v0 = img[(y + j) * WID + x];
        const float v1 = img[WID * WID + (y + j) * WID + x];
        g_pairN[(y + j) * WID + x] = make_float2(v0, v1);
        t0[threadIdx.y + j][threadIdx.x] = v0;
        t1[threadIdx.y + j][threadIdx.x] = v1;
    }
    __syncthreads();

    x = blockIdx.y * 32 + threadIdx.x;
    y = blockIdx.x * 32 + threadIdx.y;
#pragma unroll
    for (int j = 0; j < 32; j += 8)
        g_pairT[(y + j) * WID + x] =
            make_float2(t0[threadIdx.x][threadIdx.y + j],
                        t1[threadIdx.x][threadIdx.y + j]);
}

// one bilinear sample accumulation; GUARDED=false assumes all 4 corners in-image.
template<bool GUARDED>
__device__ __forceinline__ void radon_step(
    const float2* __restrict__ pp, float xx, float yy, float& sum0, float& sum1)
{
    const float fx0 = floorf(xx);
    const float fy0 = floorf(yy);
    const float tx = xx - fx0;
    const float ty = yy - fy0;

    const int x0 = (int)fx0;
    const int y0 = (int)fy0;
    const int base = y0 * WID + x0;

    float2 A, B, C, D;
    if (GUARDED) {
        const bool vx0 = (unsigned)x0       < (unsigned)WID;
        const bool vx1 = (unsigned)(x0 + 1) < (unsigned)WID;
        const bool vy0 = (unsigned)y0       < (unsigned)WID;
        const bool vy1 = (unsigned)(y0 + 1) < (unsigned)WID;
        A = make_float2(0.f, 0.f); B = A; C = A; D = A;
        if (vy0 & vx0) A = __ldg(pp + base);
        if (vy0 & vx1) B = __ldg(pp + base + 1);
        if (vy1 & vx0) C = __ldg(pp + base + WID);
        if (vy1 & vx1) D = __ldg(pp + base + WID + 1);
    } else {
        A = __ldg(pp + base);
        B = __ldg(pp + base + 1);
        C = __ldg(pp + base + WID);
        D = __ldg(pp + base + WID + 1);
    }

    const float top0 = fmaf(tx, B.x - A.x, A.x);
    const float bot0 = fmaf(tx, D.x - C.x, C.x);
    const float top1 = fmaf(tx, B.y - A.y, A.y);
    const float bot1 = fmaf(tx, D.y - C.y, C.y);

    sum0 += fmaf(ty, bot0 - top0, top0);
    sum1 += fmaf(ty, bot1 - top1, top1);
}

// ── main kernel ── grid (2, NT, SEG), block 256; each thread: one column c, both batches.
__global__ __launch_bounds__(256) void radon_part_kernel()
{
    const int t   = blockIdx.y;
    const int seg = blockIdx.z;
    const int c   = blockIdx.x * 256 + threadIdx.x;

    const float th = (float)t * 0.017453292519943295f;
    float s, co;
    sincosf(th, &s, &co);

    const float u = (float)c - 255.5f;
    const float ix0 = fmaf(co, u, fmaf(s, -255.5f, 255.5f));
    const float iy0 = fmaf(-s, u, fmaf(co, -255.5f, 255.5f));

    const bool steep = fabsf(s) > fabsf(co);
    float x0c, y0c, stepx, stepy;
    const float2* __restrict__ pp;
    if (!steep) { x0c = ix0; y0c = iy0; stepx = s;  stepy = co; pp = g_pairN; }
    else        { x0c = iy0; y0c = ix0; stepx = co; stepy = s;  pp = g_pairT; }

    // outer clip: contribution possible iff coord in (-1, 512) on both axes.
    // interior: all 4 corners valid, guaranteed by coord in [1, 510] (1px margin).
    float lo = 0.0f, hi = (float)WID;       // outer
    float ilo = 0.0f, ihi = (float)WID;     // interior
    {
        if (fabsf(stepx) < 1e-6f) {
            if (x0c <= -1.0f || x0c >= (float)WID) { lo = 1.0f; hi = 0.0f; }
            if (x0c < 1.0f || x0c > 510.0f) { ilo = 1.0f; ihi = 0.0f; }
        } else {
            const float inv = 1.0f / stepx;
            float a = (-1.0f - x0c) * inv, b = ((float)WID - x0c) * inv;
            lo = fmaxf(lo, fminf(a, b)); hi = fminf(hi, fmaxf(a, b));
            a = (1.0f - x0c) * inv; b = (510.0f - x0c) * inv;
            ilo = fmaxf(ilo, fminf(a, b)); ihi = fminf(ihi, fmaxf(a, b));
        }
        if (fabsf(stepy) < 1e-6f) {
            if (y0c <= -1.0f || y0c >= (float)WID) { lo = 1.0f; hi = 0.0f; }
            if (y0c < 1.0f || y0c > 510.0f) { ilo = 1.0f; ihi = 0.0f; }
        } else {
            const float inv = 1.0f / stepy;
            float a = (-1.0f - y0c) * inv, b = ((float)WID - y0c) * inv;
            lo = fmaxf(lo, fminf(a, b)); hi = fminf(hi, fmaxf(a, b));
            a = (1.0f - y0c) * inv; b = (510.0f - y0c) * inv;
            ilo = fmaxf(ilo, fminf(a, b)); ihi = fminf(ihi, fmaxf(a, b));
        }
    }
    const int rbeg = seg * RPS;
    int r0 = rbeg, r1 = rbeg + RPS;
    if (lo > (float)r0 + 1.0f) r0 = (int)floorf(lo) - 1;
    if (hi < (float)r1 - 1.0f) r1 = (int)ceilf(hi) + 1;
    if (r1 > rbeg + RPS) r1 = rbeg + RPS;
    if (r0 < rbeg) r0 = rbeg;

    // interior subrange [ri0, ri1) within [r0, r1)
    int ri0 = (int)ceilf(ilo);
    int ri1 = (int)floorf(ihi) + 1;
    ri0 = max(ri0, r0); ri0 = min(ri0, r1);
    ri1 = min(ri1, r1); ri1 = max(ri1, ri0);

    float sum0 = 0.0f, sum1 = 0.0f;

    for (int r = r0; r < ri0; ++r)
        radon_step<true >(pp, fmaf((float)r, stepx, x0c), fmaf((float)r, stepy, y0c), sum0, sum1);
#pragma unroll 8
    for (int r = ri0; r < ri1; ++r)
        radon_step<false>(pp, fmaf((float)r, stepx, x0c), fmaf((float)r, stepy, y0c), sum0, sum1);
    for (int r = ri1; r < r1; ++r)
        radon_step<true >(pp, fmaf((float)r, stepx, x0c), fmaf((float)r, stepy, y0c), sum0, sum1);

    g_scratch[((seg * 2 + 0) * WID + c) * NT + t] = sum0;
    g_scratch[((seg * 2 + 1) * WID + c) * NT + t] = sum1;
}

// out[n][c][t] = (1/512) * sum_seg scratch[seg][n][c][t]
__global__ __launch_bounds__(256) void radon_reduce_kernel(
    float* __restrict__ out)         // [2, 512, 180] = 184320 elems
{
    const int i = blockIdx.x * 256 + threadIdx.x;
    const int n   = i / (WID * NT);
    const int rem = i - n * (WID * NT);

    float acc = 0.0f;
#pragma unroll
    for (int seg = 0; seg < SEG; ++seg)
        acc += g_scratch[(seg * 2 + n) * (WID * NT) + rem];

    out[i] = acc * (1.0f / (float)WID);
}

extern "C" void kernel_launch(void* const* d_in, const int* in_sizes, int n_in,
                              void* d_out, int out_size)
{
    const float* x = (const float*)d_in[0];   // [2,1,512,512] fp32
    float* out = (float*)d_out;               // [2,1,512,180] fp32

    pack_kernel<<<dim3(16, 16), dim3(32, 8)>>>(x);
    radon_part_kernel<<<dim3(2, NT, SEG), 256>>>();
    radon_reduce_kernel<<<(2 * WID * NT) / 256, 256>>>(out);
}